// round 3
// baseline (speedup 1.0000x reference)
#include <cuda_runtime.h>
#include <math.h>
#include <stdint.h>

// ---------------- problem constants ----------------
#define BATCH    2
#define SEQ      4096
#define DMODEL   2048
#define DSTATE   64
#define HEADDIM  128
#define CHUNK    256
#define DINNER   4096
#define NHEADS   32
#define CONVDIM  4224               // DINNER + 2*DSTATE
#define DPROJ    8352               // 2*DINNER + 2*DSTATE + NHEADS
#define NCHUNK   16                 // SEQ / CHUNK
#define TOKENS   (BATCH*SEQ)        // 8192
#define LN_EPS   1e-5f

// ---------------- device scratch (no cudaMalloc allowed) ----------------
__device__ float g_zx [(size_t)TOKENS * DPROJ];    // in_proj output
__device__ float g_xbc[(size_t)TOKENS * CONVDIM];  // conv+silu output
__device__ float g_dt [TOKENS * NHEADS];           // softplus(dt)
__device__ float g_cA [BATCH*NCHUNK*NHEADS*CHUNK]; // per-chunk cumsum of A*dt
__device__ float g_st [BATCH*NCHUNK*NHEADS*HEADDIM*DSTATE]; // chunk states
__device__ float g_stP[BATCH*NCHUNK*NHEADS*HEADDIM*DSTATE]; // prefix states
__device__ float g_y  [(size_t)TOKENS * DINNER];   // SSD output / LN inout

// ================= 3xTF32 tensor-core GEMM =================
// C[M,N] = A[M,K] @ W[N,K]^T + bias.  M%128==0, K%32==0, N arbitrary.
// 256 threads, block tile 128x128x32, warp tile 64x32, mma.m16n8k8.tf32,
// 3xTF32 split for ~fp32 accuracy. cp.async double-buffered smem.

__device__ __forceinline__ uint32_t f2tf32(float x) {
    uint32_t r; asm("cvt.rna.tf32.f32 %0, %1;" : "=r"(r) : "f"(x)); return r;
}
__device__ __forceinline__ void cp_async16(uint32_t dst, const void* src, int sz) {
    asm volatile("cp.async.ca.shared.global [%0], [%1], 16, %2;\n"
                 :: "r"(dst), "l"(src), "r"(sz));
}
#define CP_COMMIT() asm volatile("cp.async.commit_group;\n")
#define CP_WAIT1()  asm volatile("cp.async.wait_group 1;\n")
#define CP_WAIT0()  asm volatile("cp.async.wait_group 0;\n")

#define MMA_TF32(d, a0,a1,a2,a3, b0,b1)                                      \
    asm volatile("mma.sync.aligned.m16n8k8.row.col.f32.tf32.tf32.f32 "       \
        "{%0,%1,%2,%3}, {%4,%5,%6,%7}, {%8,%9}, {%0,%1,%2,%3};"              \
        : "+f"(d[0]), "+f"(d[1]), "+f"(d[2]), "+f"(d[3])                     \
        : "r"(a0), "r"(a1), "r"(a2), "r"(a3), "r"(b0), "r"(b1))

#define LDPAD 36   // 36 % 32 == 4 -> fragment LDS banks = 4*gid+tig (conflict-free)

__global__ __launch_bounds__(256) void gemm3x_kernel(
    const float* __restrict__ A, const float* __restrict__ W,
    const float* __restrict__ bias, float* __restrict__ C,
    int M, int N, int K)
{
    extern __shared__ float sh[];
    float* As = sh;                       // [2][128][LDPAD]
    float* Ws = sh + 2*128*LDPAD;         // [2][128][LDPAD]
    const uint32_t as_base = (uint32_t)__cvta_generic_to_shared(As);
    const uint32_t ws_base = (uint32_t)__cvta_generic_to_shared(Ws);

    const int t    = threadIdx.x;
    const int bm   = blockIdx.y * 128;
    const int bn   = blockIdx.x * 128;
    const int lane = t & 31;
    const int warp = t >> 5;
    const int wm   = (warp >> 2) * 64;
    const int wn   = (warp & 3) * 32;
    const int gid  = lane >> 2, tig = lane & 3;

    const int ldr = t >> 3;               // 0..31
    const int ldc = (t & 7) * 4;          // 0,4,...,28

    float acc[4][4][4];
#pragma unroll
    for (int i = 0; i < 4; i++)
#pragma unroll
        for (int j = 0; j < 4; j++)
#pragma unroll
            for (int k = 0; k < 4; k++) acc[i][j][k] = 0.f;

    const int nk = K / 32;

    // ---- prologue: load stage 0 ----
    {
#pragma unroll
        for (int p = 0; p < 4; p++) {
            int row = p*32 + ldr;
            cp_async16(as_base + (uint32_t)((row*LDPAD + ldc)*4),
                       A + (size_t)(bm + row)*K + ldc, 16);
        }
#pragma unroll
        for (int p = 0; p < 4; p++) {
            int row = p*32 + ldr;
            int n   = bn + row;
            int ok  = (n < N);
            const float* src = W + (size_t)(ok ? n : 0)*K + ldc;
            cp_async16(ws_base + (uint32_t)((row*LDPAD + ldc)*4),
                       src, ok ? 16 : 0);
        }
        CP_COMMIT();
    }

    for (int kb = 0; kb < nk; kb++) {
        // prefetch next stage
        if (kb + 1 < nk) {
            const int stg = (kb + 1) & 1;
#pragma unroll
            for (int p = 0; p < 4; p++) {
                int row = p*32 + ldr;
                cp_async16(as_base + (uint32_t)(((stg*128 + row)*LDPAD + ldc)*4),
                           A + (size_t)(bm + row)*K + (kb+1)*32 + ldc, 16);
            }
#pragma unroll
            for (int p = 0; p < 4; p++) {
                int row = p*32 + ldr;
                int n   = bn + row;
                int ok  = (n < N);
                const float* src = W + (size_t)(ok ? n : 0)*K + (kb+1)*32 + ldc;
                cp_async16(ws_base + (uint32_t)(((stg*128 + row)*LDPAD + ldc)*4),
                           src, ok ? 16 : 0);
            }
            CP_COMMIT();
            CP_WAIT1();
        } else {
            CP_WAIT0();
        }
        __syncthreads();

        const float* as = As + (kb & 1)*128*LDPAD;
        const float* ws = Ws + (kb & 1)*128*LDPAD;

#pragma unroll
        for (int kk = 0; kk < 4; kk++) {
            const int k8 = kk*8;
            uint32_t bh[4][2], bl[4][2];
#pragma unroll
            for (int nt = 0; nt < 4; nt++) {
                float r0 = ws[(wn + nt*8 + gid)*LDPAD + k8 + tig];
                float r1 = ws[(wn + nt*8 + gid)*LDPAD + k8 + tig + 4];
                bh[nt][0] = f2tf32(r0);
                bl[nt][0] = f2tf32(r0 - __uint_as_float(bh[nt][0]));
                bh[nt][1] = f2tf32(r1);
                bl[nt][1] = f2tf32(r1 - __uint_as_float(bh[nt][1]));
            }
#pragma unroll
            for (int mt = 0; mt < 4; mt++) {
                float r0 = as[(wm + mt*16 + gid    )*LDPAD + k8 + tig];
                float r1 = as[(wm + mt*16 + gid + 8)*LDPAD + k8 + tig];
                float r2 = as[(wm + mt*16 + gid    )*LDPAD + k8 + tig + 4];
                float r3 = as[(wm + mt*16 + gid + 8)*LDPAD + k8 + tig + 4];
                uint32_t ah0 = f2tf32(r0), ah1 = f2tf32(r1);
                uint32_t ah2 = f2tf32(r2), ah3 = f2tf32(r3);
                uint32_t al0 = f2tf32(r0 - __uint_as_float(ah0));
                uint32_t al1 = f2tf32(r1 - __uint_as_float(ah1));
                uint32_t al2 = f2tf32(r2 - __uint_as_float(ah2));
                uint32_t al3 = f2tf32(r3 - __uint_as_float(ah3));
#pragma unroll
                for (int nt = 0; nt < 4; nt++) {
                    MMA_TF32(acc[mt][nt], ah0, ah1, ah2, ah3, bh[nt][0], bh[nt][1]);
                    MMA_TF32(acc[mt][nt], al0, al1, al2, al3, bh[nt][0], bh[nt][1]);
                    MMA_TF32(acc[mt][nt], ah0, ah1, ah2, ah3, bl[nt][0], bl[nt][1]);
                }
            }
        }
        __syncthreads();
    }

    // ---- epilogue ----
#pragma unroll
    for (int mt = 0; mt < 4; mt++) {
        int r0 = bm + wm + mt*16 + gid;
#pragma unroll
        for (int nt = 0; nt < 4; nt++) {
            int c0 = bn + wn + nt*8 + tig*2;
            if (c0 < N) {   // N even, c0 even -> c0+1 also valid
                float b0v = bias[c0], b1v = bias[c0+1];
                float2 v0 = make_float2(acc[mt][nt][0] + b0v, acc[mt][nt][1] + b1v);
                float2 v1 = make_float2(acc[mt][nt][2] + b0v, acc[mt][nt][3] + b1v);
                *(float2*)&C[(size_t)r0*N + c0]     = v0;
                *(float2*)&C[(size_t)(r0+8)*N + c0] = v1;
            }
        }
    }
}

// ---------------- dt = softplus(raw + dt_bias) ----------------
__global__ void dt_kernel(const float* __restrict__ dt_bias)
{
    int idx = blockIdx.x * blockDim.x + threadIdx.x;   // TOKENS*NHEADS
    int h = idx & 31;
    int tok = idx >> 5;
    float x = g_zx[(size_t)tok*DPROJ + DINNER + CONVDIM + h] + dt_bias[h];
    g_dt[idx] = (x > 20.f) ? x : log1pf(expf(x));
}

// ---------------- causal depthwise conv (k=4) + silu, float4 over channels ----------------
__global__ void conv_silu_kernel(const float* __restrict__ cw, const float* __restrict__ cb)
{
    int idx = blockIdx.x * blockDim.x + threadIdx.x;   // TOKENS*CONVDIM/4
    int ch4 = idx % (CONVDIM/4);
    int tok = idx / (CONVDIM/4);
    int ch  = ch4 * 4;
    int l   = tok & (SEQ - 1);

    float4 a = *(const float4*)(cb + ch);
    float acc[4] = {a.x, a.y, a.z, a.w};
    float w[4][4];
#pragma unroll
    for (int c = 0; c < 4; c++)
        *(float4*)w[c] = *(const float4*)(cw + (ch + c)*4);

    const float* base = g_zx + (size_t)tok * DPROJ + DINNER + ch;
#pragma unroll
    for (int k = 0; k < 4; k++) {
        int ls = l - 3 + k;
        if (ls >= 0) {
            float4 x = *(const float4*)(base + (long)(k-3) * DPROJ);
            acc[0] += w[0][k]*x.x; acc[1] += w[1][k]*x.y;
            acc[2] += w[2][k]*x.z; acc[3] += w[3][k]*x.w;
        }
    }
    float4 o;
    o.x = acc[0] / (1.f + __expf(-acc[0]));
    o.y = acc[1] / (1.f + __expf(-acc[1]));
    o.z = acc[2] / (1.f + __expf(-acc[2]));
    o.w = acc[3] / (1.f + __expf(-acc[3]));
    *(float4*)(g_xbc + (size_t)tok * CONVDIM + ch) = o;
}

// ---------------- per-chunk inclusive cumsum of dA = A*dt ----------------
__global__ void cumsum_kernel(const float* __restrict__ A_log)
{
    __shared__ float s[CHUNK];
    int bid = blockIdx.x;                     // ((b*NCHUNK+c)*NHEADS+h)
    int h = bid & 31;
    int c = (bid >> 5) & 15;
    int b = bid >> 9;
    int l = threadIdx.x;
    int tok = b*SEQ + c*CHUNK + l;
    float Av = -expf(A_log[h]);
    s[l] = Av * g_dt[tok*NHEADS + h];
    __syncthreads();
    for (int off = 1; off < CHUNK; off <<= 1) {
        float add = (l >= off) ? s[l-off] : 0.f;
        __syncthreads();
        s[l] += add;
        __syncthreads();
    }
    g_cA[bid*CHUNK + l] = s[l];
}

// ---------------- per-chunk states: S[p,n] = sum_s decay[s]*dt[s]*x[s,p]*B[s,n] ----------------
__global__ __launch_bounds__(256) void states_kernel()
{
    extern __shared__ float sm[];
    float* sBw  = sm;            // 64*64
    float* sX   = sm + 4096;     // 64*128
    float* sdec = sX + 8192;     // 64
    float* sdtv = sdec + 64;     // 64
    int bid = blockIdx.x;
    int h = bid & 31, c = (bid >> 5) & 15, b = bid >> 9;
    int tok0 = b*SEQ + c*CHUNK;
    const float* cA = g_cA + bid*CHUNK;
    int t = threadIdx.x;
    float cAlast = cA[CHUNK-1];
    int tp = t & 31, tn = t >> 5;
    float acc[4][8];
#pragma unroll
    for (int i = 0; i < 4; i++)
#pragma unroll
        for (int j = 0; j < 8; j++) acc[i][j] = 0.f;

    for (int s0 = 0; s0 < CHUNK; s0 += 64) {
        __syncthreads();
        if (t < 64) {
            sdec[t] = __expf(cAlast - cA[s0 + t]);
            sdtv[t] = g_dt[(tok0 + s0 + t)*NHEADS + h];
        }
        __syncthreads();
#pragma unroll
        for (int i = 0; i < 16; i++) {
            int idx = i*256 + t; int s = idx >> 6, n = idx & 63;
            sBw[idx] = g_xbc[(size_t)(tok0+s0+s)*CONVDIM + DINNER + n] * sdec[s];
        }
#pragma unroll
        for (int i = 0; i < 32; i++) {
            int idx = i*256 + t; int s = idx >> 7, p = idx & 127;
            sX[idx] = g_xbc[(size_t)(tok0+s0+s)*CONVDIM + h*HEADDIM + p] * sdtv[s];
        }
        __syncthreads();
        for (int s = 0; s < 64; s++) {
            float4 xa = *(const float4*)&sX[s*128 + tp*4];
            float bb[8];
            *(float4*)&bb[0] = *(const float4*)&sBw[s*64 + tn*8];
            *(float4*)&bb[4] = *(const float4*)&sBw[s*64 + tn*8 + 4];
            float xf[4] = {xa.x, xa.y, xa.z, xa.w};
#pragma unroll
            for (int i = 0; i < 4; i++)
#pragma unroll
                for (int j = 0; j < 8; j++) acc[i][j] += xf[i]*bb[j];
        }
    }
    float* out = g_st + (size_t)bid * HEADDIM * DSTATE;
#pragma unroll
    for (int i = 0; i < 4; i++)
#pragma unroll
        for (int j = 0; j < 8; j++)
            out[(tp*4 + i)*DSTATE + tn*8 + j] = acc[i][j];
}

// ---------------- inter-chunk sequential scan (16 steps per (b,h)) ----------------
__global__ void scan_kernel()
{
    int bh = blockIdx.x;           // b*NHEADS + h
    int h = bh & 31, b = bh >> 5;
    int t = threadIdx.x;           // 256
    float P[32];
#pragma unroll
    for (int i = 0; i < 32; i++) P[i] = 0.f;
    for (int c = 0; c < NCHUNK; c++) {
        int cb = (b*NCHUNK + c)*NHEADS + h;
        float dec = __expf(g_cA[cb*CHUNK + CHUNK-1]);
        size_t sb = (size_t)cb * HEADDIM * DSTATE;
#pragma unroll
        for (int i = 0; i < 32; i++) {
            int e = i*256 + t;
            g_stP[sb + e] = P[i];
            P[i] = P[i]*dec + g_st[sb + e];
        }
    }
}

// ---------------- fused Y = (L ∘ C B^T) X·dt + exp(cumA) C S_prev^T ----------------
#define Y_PHASE2_STEP()                                                  \
    for (int s = 0; s < 64; s++) {                                       \
        float afr[8];                                                    \
        _Pragma("unroll")                                                \
        for (int i = 0; i < 8; i++) afr[i] = sG[(tl*8 + i)*65 + s];      \
        float bfr[8];                                                    \
        *(float4*)&bfr[0] = *(const float4*)&sX[s*128 + tp*8];           \
        *(float4*)&bfr[4] = *(const float4*)&sX[s*128 + tp*8 + 4];       \
        _Pragma("unroll")                                                \
        for (int i = 0; i < 8; i++)                                      \
            _Pragma("unroll")                                            \
            for (int j = 0; j < 8; j++) acc[i][j] += afr[i]*bfr[j];      \
    }

__global__ __launch_bounds__(512) void ydiag_kernel()
{
    extern __shared__ float sm[];
    float* scA   = sm;                 // 256
    float* srowf = scA + 256;          // 256
    float* scolf = srowf + 256;        // 64
    float* sdtv  = scolf + 64;         // 64
    float* sC    = sdtv + 64;          // 256*64
    float* sB    = sC + 16384;         // 64*65 (padded)
    float* sX    = sB + 4160;          // 64*128
    float* sG    = sX + 8192;          // 256*65 (padded)

    int bid = blockIdx.x;
    int h = bid & 31, c = (bid >> 5) & 15, b = bid >> 9;
    int tok0 = b*SEQ + c*CHUNK;
    int t = threadIdx.x;
    const float* cAg = g_cA + bid*CHUNK;

    const int tl = t >> 4;   // 0..31 : l-tile (8 rows each)
    const int tp = t & 15;   // 0..15 : p-tile (8 cols each)

    float acc[8][8];
#pragma unroll
    for (int i = 0; i < 8; i++)
#pragma unroll
        for (int j = 0; j < 8; j++) acc[i][j] = 0.f;

    if (t < 256) scA[t] = cAg[t];
#pragma unroll
    for (int i = 0; i < 32; i++) {
        int idx = i*512 + t; int l = idx >> 6, n = idx & 63;
        sC[idx] = g_xbc[(size_t)(tok0 + l)*CONVDIM + DINNER + DSTATE + n];
    }
    {   // S_prev transposed into sX:  sX[n*128+p] = S_prev[p,n]
        size_t sb = (size_t)bid * HEADDIM * DSTATE;
#pragma unroll
        for (int i = 0; i < 16; i++) {
            int idx = i*512 + t; int n = idx >> 7, p = idx & 127;
            sX[idx] = g_stP[sb + p*DSTATE + n];
        }
    }
    __syncthreads();
    if (t < 256) srowf[t] = __expf(scA[t]);
    __syncthreads();
#pragma unroll
    for (int i = 0; i < 32; i++) {   // G0[l,n] = C[l,n]*exp(cumA[l])
        int idx = i*512 + t; int l = idx >> 6, n = idx & 63;
        sG[l*65 + n] = sC[idx] * srowf[l];
    }
    __syncthreads();
    Y_PHASE2_STEP();                 // off-chunk contribution

    for (int s0 = 0; s0 < CHUNK; s0 += 64) {
        __syncthreads();             // previous phase-2 done
        float cAe = scA[s0 + 63];
        if (t < 64) {
            sdtv[t]  = g_dt[(tok0 + s0 + t)*NHEADS + h];
            scolf[t] = __expf(cAe - scA[s0 + t]);          // <= 1
        }
        if (t < 256) srowf[t] = __expf(scA[t] - cAe);      // used only for l >= s0+64
#pragma unroll
        for (int i = 0; i < 8; i++) {
            int idx = i*512 + t; int s = idx >> 6, n = idx & 63;
            sB[s*65 + n] = g_xbc[(size_t)(tok0+s0+s)*CONVDIM + DINNER + n];
        }
        __syncthreads();
#pragma unroll
        for (int i = 0; i < 16; i++) {
            int idx = i*512 + t; int s = idx >> 7, p = idx & 127;
            sX[idx] = g_xbc[(size_t)(tok0+s0+s)*CONVDIM + h*HEADDIM + p] * sdtv[s];
        }
        // phase 1: G[l,s] = (C[l]·B[s]) * exp(cumA[l]-cumA[s]) masked
#pragma unroll
        for (int g = 0; g < 2; g++) {
            float a1[4][4];
#pragma unroll
            for (int i = 0; i < 4; i++)
#pragma unroll
                for (int j = 0; j < 4; j++) a1[i][j] = 0.f;
            for (int n = 0; n < 64; n++) {
                float cc[4], bb[4];
#pragma unroll
                for (int i = 0; i < 4; i++) cc[i] = sC[(tl*8 + g*4 + i)*64 + n];
#pragma unroll
                for (int j = 0; j < 4; j++) bb[j] = sB[(tp*4 + j)*65 + n];
#pragma unroll
                for (int i = 0; i < 4; i++)
#pragma unroll
                    for (int j = 0; j < 4; j++) a1[i][j] += cc[i]*bb[j];
            }
#pragma unroll
            for (int i = 0; i < 4; i++) {
                int l = tl*8 + g*4 + i;
#pragma unroll
                for (int j = 0; j < 4; j++) {
                    int s  = tp*4 + j;
                    int sg = s0 + s;
                    float w;
                    if (l < sg)            w = 0.f;
                    else if (l < s0 + 64)  w = __expf(scA[l] - scA[sg]);   // diagonal tile
                    else                   w = srowf[l] * scolf[s];        // factored, both <= 1
                    sG[l*65 + s] = a1[i][j] * w;
                }
            }
        }
        __syncthreads();
        Y_PHASE2_STEP();
    }

    float* yout = g_y + (size_t)tok0 * DINNER + h*HEADDIM;
#pragma unroll
    for (int i = 0; i < 8; i++) {
        int l = tl*8 + i;
#pragma unroll
        for (int j = 0; j < 8; j += 4) {
            float4 v = make_float4(acc[i][j], acc[i][j+1], acc[i][j+2], acc[i][j+3]);
            *(float4*)&yout[(size_t)l*DINNER + tp*8 + j] = v;
        }
    }
}

// ---------------- gate (y * silu(z)) + LayerNorm, in place on g_y ----------------
__global__ __launch_bounds__(512) void gate_ln_kernel(
    const float* __restrict__ lnw, const float* __restrict__ lnb)
{
    int tok = blockIdx.x;
    int t = threadIdx.x;
    const float* zx = g_zx + (size_t)tok * DPROJ;
    float* y = g_y + (size_t)tok * DINNER;
    __shared__ float rbuf[16];
    __shared__ float stat[2];

    float v[8];
    float sum = 0.f;
#pragma unroll
    for (int i = 0; i < 8; i++) {
        int e = i*512 + t;
        float z = zx[e];
        float g = y[e] * z / (1.f + __expf(-z));
        v[i] = g; sum += g;
    }
#pragma unroll
    for (int o = 16; o; o >>= 1) sum += __shfl_xor_sync(0xffffffffu, sum, o);
    if ((t & 31) == 0) rbuf[t >> 5] = sum;
    __syncthreads();
    if (t == 0) {
        float x = 0.f;
        for (int i = 0; i < 16; i++) x += rbuf[i];
        stat[0] = x * (1.f / DINNER);
    }
    __syncthreads();
    float mu = stat[0];
    float s2 = 0.f;
#pragma unroll
    for (int i = 0; i < 8; i++) { float d = v[i] - mu; s2 += d*d; }
#pragma unroll
    for (int o = 16; o; o >>= 1) s2 += __shfl_xor_sync(0xffffffffu, s2, o);
    if ((t & 31) == 0) rbuf[t >> 5] = s2;
    __syncthreads();
    if (t == 0) {
        float x = 0.f;
        for (int i = 0; i < 16; i++) x += rbuf[i];
        stat[1] = rsqrtf(x * (1.f / DINNER) + LN_EPS);
    }
    __syncthreads();
    float inv = stat[1];
#pragma unroll
    for (int i = 0; i < 8; i++) {
        int e = i*512 + t;
        y[e] = (v[i] - mu) * inv * lnw[e] + lnb[e];
    }
}

// ---------------- launch ----------------
extern "C" void kernel_launch(void* const* d_in, const int* in_sizes, int n_in,
                              void* d_out, int out_size)
{
    const float* u       = (const float*)d_in[0];
    const float* in_w    = (const float*)d_in[1];
    const float* in_b    = (const float*)d_in[2];
    const float* conv_w  = (const float*)d_in[3];
    const float* conv_b  = (const float*)d_in[4];
    const float* dt_bias = (const float*)d_in[5];
    const float* A_log   = (const float*)d_in[6];
    const float* ln_w    = (const float*)d_in[7];
    const float* ln_b    = (const float*)d_in[8];
    const float* out_w   = (const float*)d_in[9];
    const float* out_b   = (const float*)d_in[10];
    float* out = (float*)d_out;

    void *zxp, *yp;
    cudaGetSymbolAddress(&zxp, g_zx);
    cudaGetSymbolAddress(&yp,  g_y);

    const int gemm_smem   = 2 * 2 * 128 * LDPAD * 4;                   // 73,728 B
    const int states_smem = (4096 + 8192 + 64 + 64) * 4;               // 49,664 B
    const int ydiag_smem  = (256+256+64+64 + 16384 + 4160 + 8192 + 16640) * 4; // 184,064 B
    cudaFuncSetAttribute(gemm3x_kernel,  cudaFuncAttributeMaxDynamicSharedMemorySize, gemm_smem);
    cudaFuncSetAttribute(states_kernel, cudaFuncAttributeMaxDynamicSharedMemorySize, states_smem);
    cudaFuncSetAttribute(ydiag_kernel,  cudaFuncAttributeMaxDynamicSharedMemorySize, ydiag_smem);

    // 1. in_proj GEMM: (8192 x 2048) @ (8352 x 2048)^T
    dim3 g1((DPROJ + 127)/128, TOKENS/128);
    gemm3x_kernel<<<g1, 256, gemm_smem>>>(u, in_w, in_b, (float*)zxp, TOKENS, DPROJ, DMODEL);

    // 2. dt softplus
    dt_kernel<<<(TOKENS*NHEADS)/256, 256>>>(dt_bias);

    // 3. depthwise conv + silu (float4 over channels)
    conv_silu_kernel<<<((size_t)TOKENS*(CONVDIM/4))/256, 256>>>(conv_w, conv_b);

    // 4. per-chunk cumsum of A*dt
    cumsum_kernel<<<BATCH*NCHUNK*NHEADS, CHUNK>>>(A_log);

    // 5. per-chunk states
    states_kernel<<<BATCH*NCHUNK*NHEADS, 256, states_smem>>>();

    // 6. inter-chunk scan
    scan_kernel<<<BATCH*NHEADS, 256>>>();

    // 7. fused diag + off-chunk Y
    ydiag_kernel<<<BATCH*NCHUNK*NHEADS, 512, ydiag_smem>>>();

    // 8. gate + LayerNorm
    gate_ln_kernel<<<TOKENS, 512>>>(ln_w, ln_b);

    // 9. out_proj GEMM: (8192 x 4096) @ (2048 x 4096)^T -> d_out
    dim3 g2(DMODEL/128, TOKENS/128);
    gemm3x_kernel<<<g2, 256, gemm_smem>>>((float*)yp, out_w, out_b, out, TOKENS, DMODEL, DINNER);
}

// round 4
// speedup vs baseline: 1.3951x; 1.3951x over previous
#include <cuda_runtime.h>
#include <cuda_bf16.h>
#include <math.h>
#include <stdint.h>

// ---------------- problem constants ----------------
#define BATCH    2
#define SEQ      4096
#define DMODEL   2048
#define DSTATE   64
#define HEADDIM  128
#define CHUNK    256
#define DINNER   4096
#define NHEADS   32
#define CONVDIM  4224               // DINNER + 2*DSTATE
#define DPROJ    8352               // 2*DINNER + 2*DSTATE + NHEADS
#define NCHUNK   16                 // SEQ / CHUNK
#define TOKENS   (BATCH*SEQ)        // 8192
#define LN_EPS   1e-5f

// ---------------- device scratch (no cudaMalloc allowed) ----------------
__device__ float g_zx [(size_t)TOKENS * DPROJ];    // in_proj output
__device__ float g_xbc[(size_t)TOKENS * CONVDIM];  // conv+silu output
__device__ float g_dt [TOKENS * NHEADS];           // softplus(dt)
__device__ float g_cA [BATCH*NCHUNK*NHEADS*CHUNK]; // per-chunk cumsum of A*dt
__device__ float g_st [BATCH*NCHUNK*NHEADS*HEADDIM*DSTATE]; // chunk states
__device__ float g_stP[BATCH*NCHUNK*NHEADS*HEADDIM*DSTATE]; // prefix states
__device__ float g_y  [(size_t)TOKENS * DINNER];   // SSD output (pre-LN)

// bf16 hi/mid split operands for the tensor-core GEMMs
__device__ __nv_bfloat16 g_uh [(size_t)TOKENS * DMODEL];
__device__ __nv_bfloat16 g_um [(size_t)TOKENS * DMODEL];
__device__ __nv_bfloat16 g_iwh[(size_t)DPROJ  * DMODEL];
__device__ __nv_bfloat16 g_iwm[(size_t)DPROJ  * DMODEL];
__device__ __nv_bfloat16 g_owh[(size_t)DMODEL * DINNER];
__device__ __nv_bfloat16 g_owm[(size_t)DMODEL * DINNER];
__device__ __nv_bfloat16 g_yh [(size_t)TOKENS * DINNER];
__device__ __nv_bfloat16 g_ym [(size_t)TOKENS * DINNER];

// ---------------- helpers ----------------
__device__ __forceinline__ void bsplit(float x, __nv_bfloat16& h, __nv_bfloat16& m) {
    h = __float2bfloat16(x);
    m = __float2bfloat16(x - __bfloat162float(h));
}
__device__ __forceinline__ void cp_async16(uint32_t dst, const void* src, int sz) {
    asm volatile("cp.async.ca.shared.global [%0], [%1], 16, %2;\n"
                 :: "r"(dst), "l"(src), "r"(sz));
}
#define CP_COMMIT() asm volatile("cp.async.commit_group;\n")
#define CP_WAIT1()  asm volatile("cp.async.wait_group 1;\n")
#define CP_WAIT0()  asm volatile("cp.async.wait_group 0;\n")

#define MMA_BF16(d, a0,a1,a2,a3, b0,b1)                                      \
    asm volatile("mma.sync.aligned.m16n8k16.row.col.f32.bf16.bf16.f32 "      \
        "{%0,%1,%2,%3}, {%4,%5,%6,%7}, {%8,%9}, {%0,%1,%2,%3};"              \
        : "+f"(d[0]), "+f"(d[1]), "+f"(d[2]), "+f"(d[3])                     \
        : "r"(a0), "r"(a1), "r"(a2), "r"(a3), "r"(b0), "r"(b1))

// ---------------- split kernels: f32 -> (bf16 hi, bf16 mid) ----------------
__global__ void split_kernel(const float* __restrict__ src,
                             __nv_bfloat16* __restrict__ hi,
                             __nv_bfloat16* __restrict__ mid, size_t n2)
{
    size_t i = (size_t)blockIdx.x * blockDim.x + threadIdx.x;
    if (i >= n2) return;
    float2 v = ((const float2*)src)[i];
    __nv_bfloat16 h0, m0, h1, m1;
    bsplit(v.x, h0, m0); bsplit(v.y, h1, m1);
    ((__nv_bfloat162*)hi)[i]  = __halves2bfloat162(h0, h1);
    ((__nv_bfloat162*)mid)[i] = __halves2bfloat162(m0, m1);
}

// ================= bf16x3 tensor-core GEMM =================
// C[M,N] = A[M,K] @ W[N,K]^T + bias, where A ~ Ah+Am, W ~ Wh+Wm (bf16 splits).
// D += Ah*Wh + Ah*Wm + Am*Wh  (error ~3*2^-16, fp32-like).
// 256 threads, block tile 128x128x32, warp tile 64x32, mma.m16n8k16.bf16.
// smem rows padded to 40 bf16 (stride 20 words) -> conflict-free fragment LDS.

#define SW 20                 // smem row stride in 32-bit words
#define TSZ (128*40)          // bf16 elements per tile array

__global__ __launch_bounds__(256) void gemm_bf16x3_kernel(
    const __nv_bfloat16* __restrict__ Ah, const __nv_bfloat16* __restrict__ Am,
    const __nv_bfloat16* __restrict__ Wh, const __nv_bfloat16* __restrict__ Wm,
    const float* __restrict__ bias, float* __restrict__ C,
    int M, int N, int K)
{
    extern __shared__ __nv_bfloat16 sh[];   // [2 stages][4 arrays][128][40]
    const uint32_t sm_base = (uint32_t)__cvta_generic_to_shared(sh);

    const int t    = threadIdx.x;
    const int bm   = blockIdx.y * 128;
    const int bn   = blockIdx.x * 128;
    const int lane = t & 31;
    const int warp = t >> 5;
    const int wm   = (warp >> 2) * 64;
    const int wn   = (warp & 3) * 32;
    const int gid  = lane >> 2, tig = lane & 3;

    const int lrow = t >> 2;       // 0..63
    const int lch  = t & 3;        // 16B chunk within a 64B row

    float acc[4][4][4];
#pragma unroll
    for (int i = 0; i < 4; i++)
#pragma unroll
        for (int j = 0; j < 4; j++)
#pragma unroll
            for (int k = 0; k < 4; k++) acc[i][j][k] = 0.f;

    const int nk = K / 32;

#define LOAD_STAGE(stg, kb) do {                                                       \
    _Pragma("unroll")                                                                  \
    for (int p = 0; p < 2; p++) {                                                      \
        int r = p*64 + lrow;                                                           \
        uint32_t db = sm_base + (uint32_t)(((stg)*4*TSZ + r*40)*2 + lch*16);           \
        cp_async16(db,         Ah + (size_t)(bm + r)*K + (kb)*32 + lch*8, 16);         \
        cp_async16(db + TSZ*2, Am + (size_t)(bm + r)*K + (kb)*32 + lch*8, 16);         \
        int ok = (bn + r) < N;                                                         \
        const __nv_bfloat16* wsh = Wh + (size_t)(ok ? (bn + r) : 0)*K + (kb)*32 + lch*8; \
        const __nv_bfloat16* wsm = Wm + (size_t)(ok ? (bn + r) : 0)*K + (kb)*32 + lch*8; \
        cp_async16(db + 2*TSZ*2, wsh, ok ? 16 : 0);                                    \
        cp_async16(db + 3*TSZ*2, wsm, ok ? 16 : 0);                                    \
    }                                                                                  \
    CP_COMMIT(); } while (0)

    LOAD_STAGE(0, 0);

    for (int kb = 0; kb < nk; kb++) {
        if (kb + 1 < nk) {
            LOAD_STAGE((kb + 1) & 1, kb + 1);
            CP_WAIT1();
        } else {
            CP_WAIT0();
        }
        __syncthreads();

        const uint32_t* ahw = (const uint32_t*)(sh + (size_t)(kb & 1)*4*TSZ);
        const uint32_t* amw = ahw + TSZ/2;
        const uint32_t* whw = ahw + TSZ;
        const uint32_t* wmw = ahw + 3*(TSZ/2);

#pragma unroll
        for (int kk = 0; kk < 2; kk++) {
            const int kof = kk*8 + tig;
            uint32_t bh[4][2], bm_[4][2];
#pragma unroll
            for (int nt = 0; nt < 4; nt++) {
                int r = (wn + nt*8 + gid)*SW + kof;
                bh[nt][0]  = whw[r];     bh[nt][1]  = whw[r + 4];
                bm_[nt][0] = wmw[r];     bm_[nt][1] = wmw[r + 4];
            }
#pragma unroll
            for (int mt = 0; mt < 4; mt++) {
                int r0 = (wm + mt*16 + gid)*SW + kof;
                uint32_t a0 = ahw[r0],          a1 = ahw[r0 + 8*SW];
                uint32_t a2 = ahw[r0 + 4],      a3 = ahw[r0 + 8*SW + 4];
                uint32_t m0 = amw[r0],          m1 = amw[r0 + 8*SW];
                uint32_t m2 = amw[r0 + 4],      m3 = amw[r0 + 8*SW + 4];
#pragma unroll
                for (int nt = 0; nt < 4; nt++) {
                    MMA_BF16(acc[mt][nt], a0, a1, a2, a3, bh[nt][0],  bh[nt][1]);
                    MMA_BF16(acc[mt][nt], a0, a1, a2, a3, bm_[nt][0], bm_[nt][1]);
                    MMA_BF16(acc[mt][nt], m0, m1, m2, m3, bh[nt][0],  bh[nt][1]);
                }
            }
        }
        __syncthreads();
    }

    // ---- epilogue (c-frag: rows gid/gid+8, cols tig*2, tig*2+1) ----
#pragma unroll
    for (int mt = 0; mt < 4; mt++) {
        int r0 = bm + wm + mt*16 + gid;
#pragma unroll
        for (int nt = 0; nt < 4; nt++) {
            int c0 = bn + wn + nt*8 + tig*2;
            if (c0 < N) {   // N even, c0 even -> c0+1 also valid
                float b0v = bias[c0], b1v = bias[c0+1];
                float2 v0 = make_float2(acc[mt][nt][0] + b0v, acc[mt][nt][1] + b1v);
                float2 v1 = make_float2(acc[mt][nt][2] + b0v, acc[mt][nt][3] + b1v);
                *(float2*)&C[(size_t)r0*N + c0]     = v0;
                *(float2*)&C[(size_t)(r0+8)*N + c0] = v1;
            }
        }
    }
}

// ---------------- fp32 GEMM for the dt head (32 cols) + softplus ----------------
// dt must stay fp32-accurate: its error is exponentially amplified via cumsum+exp.
__global__ __launch_bounds__(256) void dtgemm_kernel(
    const float* __restrict__ u, const float* __restrict__ w,
    const float* __restrict__ in_b, const float* __restrict__ dt_bias)
{
    int warp = threadIdx.x >> 5, lane = threadIdx.x & 31;
    int tok = blockIdx.x * 8 + warp;
    const float4* u4 = (const float4*)(u + (size_t)tok * DMODEL);
    const float4* w4 = (const float4*)(w + (size_t)(DINNER + CONVDIM + lane) * DMODEL);
    float acc = 0.f;
#pragma unroll 4
    for (int k = 0; k < DMODEL/4; k++) {
        float4 a = u4[k], b = w4[k];
        acc += a.x*b.x + a.y*b.y + a.z*b.z + a.w*b.w;
    }
    float x = acc + in_b[DINNER + CONVDIM + lane] + dt_bias[lane];
    g_dt[tok*NHEADS + lane] = (x > 20.f) ? x : log1pf(expf(x));
}

// ---------------- causal depthwise conv (k=4) + silu, float4 over channels ----------------
__global__ void conv_silu_kernel(const float* __restrict__ cw, const float* __restrict__ cb)
{
    int idx = blockIdx.x * blockDim.x + threadIdx.x;   // TOKENS*CONVDIM/4
    int ch4 = idx % (CONVDIM/4);
    int tok = idx / (CONVDIM/4);
    int ch  = ch4 * 4;
    int l   = tok & (SEQ - 1);

    float4 a = *(const float4*)(cb + ch);
    float acc[4] = {a.x, a.y, a.z, a.w};
    float w[4][4];
#pragma unroll
    for (int c = 0; c < 4; c++)
        *(float4*)w[c] = *(const float4*)(cw + (ch + c)*4);

    const float* base = g_zx + (size_t)tok * DPROJ + DINNER + ch;
#pragma unroll
    for (int k = 0; k < 4; k++) {
        int ls = l - 3 + k;
        if (ls >= 0) {
            float4 x = *(const float4*)(base + (long)(k-3) * DPROJ);
            acc[0] += w[0][k]*x.x; acc[1] += w[1][k]*x.y;
            acc[2] += w[2][k]*x.z; acc[3] += w[3][k]*x.w;
        }
    }
    float4 o;
    o.x = acc[0] / (1.f + __expf(-acc[0]));
    o.y = acc[1] / (1.f + __expf(-acc[1]));
    o.z = acc[2] / (1.f + __expf(-acc[2]));
    o.w = acc[3] / (1.f + __expf(-acc[3]));
    *(float4*)(g_xbc + (size_t)tok * CONVDIM + ch) = o;
}

// ---------------- per-chunk inclusive cumsum of dA = A*dt ----------------
__global__ void cumsum_kernel(const float* __restrict__ A_log)
{
    __shared__ float s[CHUNK];
    int bid = blockIdx.x;                     // ((b*NCHUNK+c)*NHEADS+h)
    int h = bid & 31;
    int c = (bid >> 5) & 15;
    int b = bid >> 9;
    int l = threadIdx.x;
    int tok = b*SEQ + c*CHUNK + l;
    float Av = -expf(A_log[h]);
    s[l] = Av * g_dt[tok*NHEADS + h];
    __syncthreads();
    for (int off = 1; off < CHUNK; off <<= 1) {
        float add = (l >= off) ? s[l-off] : 0.f;
        __syncthreads();
        s[l] += add;
        __syncthreads();
    }
    g_cA[bid*CHUNK + l] = s[l];
}

// ---------------- per-chunk states: S[p,n] = sum_s decay[s]*dt[s]*x[s,p]*B[s,n] ----------------
__global__ __launch_bounds__(256) void states_kernel()
{
    extern __shared__ float sm[];
    float* sBw  = sm;            // 64*64
    float* sX   = sm + 4096;     // 64*128
    float* sdec = sX + 8192;     // 64
    float* sdtv = sdec + 64;     // 64
    int bid = blockIdx.x;
    int h = bid & 31, c = (bid >> 5) & 15, b = bid >> 9;
    int tok0 = b*SEQ + c*CHUNK;
    const float* cA = g_cA + bid*CHUNK;
    int t = threadIdx.x;
    float cAlast = cA[CHUNK-1];
    int tp = t & 31, tn = t >> 5;
    float acc[4][8];
#pragma unroll
    for (int i = 0; i < 4; i++)
#pragma unroll
        for (int j = 0; j < 8; j++) acc[i][j] = 0.f;

    for (int s0 = 0; s0 < CHUNK; s0 += 64) {
        __syncthreads();
        if (t < 64) {
            sdec[t] = __expf(cAlast - cA[s0 + t]);
            sdtv[t] = g_dt[(tok0 + s0 + t)*NHEADS + h];
        }
        __syncthreads();
#pragma unroll
        for (int i = 0; i < 16; i++) {
            int idx = i*256 + t; int s = idx >> 6, n = idx & 63;
            sBw[idx] = g_xbc[(size_t)(tok0+s0+s)*CONVDIM + DINNER + n] * sdec[s];
        }
#pragma unroll
        for (int i = 0; i < 32; i++) {
            int idx = i*256 + t; int s = idx >> 7, p = idx & 127;
            sX[idx] = g_xbc[(size_t)(tok0+s0+s)*CONVDIM + h*HEADDIM + p] * sdtv[s];
        }
        __syncthreads();
        for (int s = 0; s < 64; s++) {
            float4 xa = *(const float4*)&sX[s*128 + tp*4];
            float bb[8];
            *(float4*)&bb[0] = *(const float4*)&sBw[s*64 + tn*8];
            *(float4*)&bb[4] = *(const float4*)&sBw[s*64 + tn*8 + 4];
            float xf[4] = {xa.x, xa.y, xa.z, xa.w};
#pragma unroll
            for (int i = 0; i < 4; i++)
#pragma unroll
                for (int j = 0; j < 8; j++) acc[i][j] += xf[i]*bb[j];
        }
    }
    float* out = g_st + (size_t)bid * HEADDIM * DSTATE;
#pragma unroll
    for (int i = 0; i < 4; i++)
#pragma unroll
        for (int j = 0; j < 8; j++)
            out[(tp*4 + i)*DSTATE + tn*8 + j] = acc[i][j];
}

// ---------------- inter-chunk sequential scan (16 steps per (b,h)) ----------------
__global__ void scan_kernel()
{
    int bh = blockIdx.x;           // b*NHEADS + h
    int h = bh & 31, b = bh >> 5;
    int t = threadIdx.x;           // 256
    float P[32];
#pragma unroll
    for (int i = 0; i < 32; i++) P[i] = 0.f;
    for (int c = 0; c < NCHUNK; c++) {
        int cb = (b*NCHUNK + c)*NHEADS + h;
        float dec = __expf(g_cA[cb*CHUNK + CHUNK-1]);
        size_t sb = (size_t)cb * HEADDIM * DSTATE;
#pragma unroll
        for (int i = 0; i < 32; i++) {
            int e = i*256 + t;
            g_stP[sb + e] = P[i];
            P[i] = P[i]*dec + g_st[sb + e];
        }
    }
}

// ---------------- fused Y = (L ∘ C B^T) X·dt + exp(cumA) C S_prev^T ----------------
#define Y_PHASE2_STEP()                                                  \
    for (int s = 0; s < 64; s++) {                                       \
        float afr[8];                                                    \
        _Pragma("unroll")                                                \
        for (int i = 0; i < 8; i++) afr[i] = sG[(tl*8 + i)*65 + s];      \
        float bfr[8];                                                    \
        *(float4*)&bfr[0] = *(const float4*)&sX[s*128 + tp*8];           \
        *(float4*)&bfr[4] = *(const float4*)&sX[s*128 + tp*8 + 4];       \
        _Pragma("unroll")                                                \
        for (int i = 0; i < 8; i++)                                      \
            _Pragma("unroll")                                            \
            for (int j = 0; j < 8; j++) acc[i][j] += afr[i]*bfr[j];      \
    }

__global__ __launch_bounds__(512) void ydiag_kernel()
{
    extern __shared__ float sm[];
    float* scA   = sm;                 // 256
    float* srowf = scA + 256;          // 256
    float* scolf = srowf + 256;        // 64
    float* sdtv  = scolf + 64;         // 64
    float* sC    = sdtv + 64;          // 256*64
    float* sB    = sC + 16384;         // 64*65 (padded)
    float* sX    = sB + 4160;          // 64*128
    float* sG    = sX + 8192;          // 256*65 (padded)

    int bid = blockIdx.x;
    int h = bid & 31, c = (bid >> 5) & 15, b = bid >> 9;
    int tok0 = b*SEQ + c*CHUNK;
    int t = threadIdx.x;
    const float* cAg = g_cA + bid*CHUNK;

    const int tl = t >> 4;   // 0..31 : l-tile (8 rows each)
    const int tp = t & 15;   // 0..15 : p-tile (8 cols each)

    float acc[8][8];
#pragma unroll
    for (int i = 0; i < 8; i++)
#pragma unroll
        for (int j = 0; j < 8; j++) acc[i][j] = 0.f;

    if (t < 256) scA[t] = cAg[t];
#pragma unroll
    for (int i = 0; i < 32; i++) {
        int idx = i*512 + t; int l = idx >> 6, n = idx & 63;
        sC[idx] = g_xbc[(size_t)(tok0 + l)*CONVDIM + DINNER + DSTATE + n];
    }
    {   // S_prev transposed into sX:  sX[n*128+p] = S_prev[p,n]
        size_t sb = (size_t)bid * HEADDIM * DSTATE;
#pragma unroll
        for (int i = 0; i < 16; i++) {
            int idx = i*512 + t; int n = idx >> 7, p = idx & 127;
            sX[idx] = g_stP[sb + p*DSTATE + n];
        }
    }
    __syncthreads();
    if (t < 256) srowf[t] = __expf(scA[t]);
    __syncthreads();
#pragma unroll
    for (int i = 0; i < 32; i++) {   // G0[l,n] = C[l,n]*exp(cumA[l])
        int idx = i*512 + t; int l = idx >> 6, n = idx & 63;
        sG[l*65 + n] = sC[idx] * srowf[l];
    }
    __syncthreads();
    Y_PHASE2_STEP();                 // off-chunk contribution

    for (int s0 = 0; s0 < CHUNK; s0 += 64) {
        __syncthreads();             // previous phase-2 done
        float cAe = scA[s0 + 63];
        if (t < 64) {
            sdtv[t]  = g_dt[(tok0 + s0 + t)*NHEADS + h];
            scolf[t] = __expf(cAe - scA[s0 + t]);          // <= 1
        }
        if (t < 256) srowf[t] = __expf(scA[t] - cAe);      // used only for l >= s0+64
#pragma unroll
        for (int i = 0; i < 8; i++) {
            int idx = i*512 + t; int s = idx >> 6, n = idx & 63;
            sB[s*65 + n] = g_xbc[(size_t)(tok0+s0+s)*CONVDIM + DINNER + n];
        }
        __syncthreads();
#pragma unroll
        for (int i = 0; i < 16; i++) {
            int idx = i*512 + t; int s = idx >> 7, p = idx & 127;
            sX[idx] = g_xbc[(size_t)(tok0+s0+s)*CONVDIM + h*HEADDIM + p] * sdtv[s];
        }
        // phase 1: G[l,s] = (C[l]·B[s]) * exp(cumA[l]-cumA[s]) masked
#pragma unroll
        for (int g = 0; g < 2; g++) {
            float a1[4][4];
#pragma unroll
            for (int i = 0; i < 4; i++)
#pragma unroll
                for (int j = 0; j < 4; j++) a1[i][j] = 0.f;
            for (int n = 0; n < 64; n++) {
                float cc[4], bb[4];
#pragma unroll
                for (int i = 0; i < 4; i++) cc[i] = sC[(tl*8 + g*4 + i)*64 + n];
#pragma unroll
                for (int j = 0; j < 4; j++) bb[j] = sB[(tp*4 + j)*65 + n];
#pragma unroll
                for (int i = 0; i < 4; i++)
#pragma unroll
                    for (int j = 0; j < 4; j++) a1[i][j] += cc[i]*bb[j];
            }
#pragma unroll
            for (int i = 0; i < 4; i++) {
                int l = tl*8 + g*4 + i;
#pragma unroll
                for (int j = 0; j < 4; j++) {
                    int s  = tp*4 + j;
                    int sg = s0 + s;
                    float w;
                    if (l < sg)            w = 0.f;
                    else if (l < s0 + 64)  w = __expf(scA[l] - scA[sg]);   // diagonal tile
                    else                   w = srowf[l] * scolf[s];        // factored, both <= 1
                    sG[l*65 + s] = a1[i][j] * w;
                }
            }
        }
        __syncthreads();
        Y_PHASE2_STEP();
    }

    float* yout = g_y + (size_t)tok0 * DINNER + h*HEADDIM;
#pragma unroll
    for (int i = 0; i < 8; i++) {
        int l = tl*8 + i;
#pragma unroll
        for (int j = 0; j < 8; j += 4) {
            float4 v = make_float4(acc[i][j], acc[i][j+1], acc[i][j+2], acc[i][j+3]);
            *(float4*)&yout[(size_t)l*DINNER + tp*8 + j] = v;
        }
    }
}

// ---------------- gate (y * silu(z)) + LayerNorm -> bf16 hi/mid split ----------------
__global__ __launch_bounds__(512) void gate_ln_kernel(
    const float* __restrict__ lnw, const float* __restrict__ lnb)
{
    int tok = blockIdx.x;
    int t = threadIdx.x;
    const float* zx = g_zx + (size_t)tok * DPROJ;
    const float* y = g_y + (size_t)tok * DINNER;
    __shared__ float rbuf[16];
    __shared__ float stat[2];

    float v[8];
    float sum = 0.f;
#pragma unroll
    for (int i = 0; i < 8; i++) {
        int e = i*512 + t;
        float z = zx[e];
        float g = y[e] * z / (1.f + __expf(-z));
        v[i] = g; sum += g;
    }
#pragma unroll
    for (int o = 16; o; o >>= 1) sum += __shfl_xor_sync(0xffffffffu, sum, o);
    if ((t & 31) == 0) rbuf[t >> 5] = sum;
    __syncthreads();
    if (t == 0) {
        float x = 0.f;
        for (int i = 0; i < 16; i++) x += rbuf[i];
        stat[0] = x * (1.f / DINNER);
    }
    __syncthreads();
    float mu = stat[0];
    float s2 = 0.f;
#pragma unroll
    for (int i = 0; i < 8; i++) { float d = v[i] - mu; s2 += d*d; }
#pragma unroll
    for (int o = 16; o; o >>= 1) s2 += __shfl_xor_sync(0xffffffffu, s2, o);
    if ((t & 31) == 0) rbuf[t >> 5] = s2;
    __syncthreads();
    if (t == 0) {
        float x = 0.f;
        for (int i = 0; i < 16; i++) x += rbuf[i];
        stat[1] = rsqrtf(x * (1.f / DINNER) + LN_EPS);
    }
    __syncthreads();
    float inv = stat[1];
    size_t base = (size_t)tok * DINNER;
#pragma unroll
    for (int i = 0; i < 8; i++) {
        int e = i*512 + t;
        float r = (v[i] - mu) * inv * lnw[e] + lnb[e];
        __nv_bfloat16 h, m;
        bsplit(r, h, m);
        g_yh[base + e] = h;
        g_ym[base + e] = m;
    }
}

// ---------------- launch ----------------
extern "C" void kernel_launch(void* const* d_in, const int* in_sizes, int n_in,
                              void* d_out, int out_size)
{
    const float* u       = (const float*)d_in[0];
    const float* in_w    = (const float*)d_in[1];
    const float* in_b    = (const float*)d_in[2];
    const float* conv_w  = (const float*)d_in[3];
    const float* conv_b  = (const float*)d_in[4];
    const float* dt_bias = (const float*)d_in[5];
    const float* A_log   = (const float*)d_in[6];
    const float* ln_w    = (const float*)d_in[7];
    const float* ln_b    = (const float*)d_in[8];
    const float* out_w   = (const float*)d_in[9];
    const float* out_b   = (const float*)d_in[10];
    float* out = (float*)d_out;

    void *zxp, *uhp, *ump, *iwhp, *iwmp, *owhp, *owmp, *yhp, *ymp;
    cudaGetSymbolAddress(&zxp,  g_zx);
    cudaGetSymbolAddress(&uhp,  g_uh);  cudaGetSymbolAddress(&ump,  g_um);
    cudaGetSymbolAddress(&iwhp, g_iwh); cudaGetSymbolAddress(&iwmp, g_iwm);
    cudaGetSymbolAddress(&owhp, g_owh); cudaGetSymbolAddress(&owmp, g_owm);
    cudaGetSymbolAddress(&yhp,  g_yh);  cudaGetSymbolAddress(&ymp,  g_ym);

    const int gemm_smem   = 2 * 4 * TSZ * 2;                           // 81,920 B
    const int states_smem = (4096 + 8192 + 64 + 64) * 4;               // 49,664 B
    const int ydiag_smem  = (256+256+64+64 + 16384 + 4160 + 8192 + 16640) * 4; // 184,064 B
    cudaFuncSetAttribute(gemm_bf16x3_kernel, cudaFuncAttributeMaxDynamicSharedMemorySize, gemm_smem);
    cudaFuncSetAttribute(states_kernel, cudaFuncAttributeMaxDynamicSharedMemorySize, states_smem);
    cudaFuncSetAttribute(ydiag_kernel,  cudaFuncAttributeMaxDynamicSharedMemorySize, ydiag_smem);

    // 0-2. bf16 hi/mid splits of u, in_w, out_w
    {
        size_t n2;
        n2 = (size_t)TOKENS*DMODEL/2;
        split_kernel<<<(unsigned)((n2 + 255)/256), 256>>>(u, (__nv_bfloat16*)uhp, (__nv_bfloat16*)ump, n2);
        n2 = (size_t)DPROJ*DMODEL/2;
        split_kernel<<<(unsigned)((n2 + 255)/256), 256>>>(in_w, (__nv_bfloat16*)iwhp, (__nv_bfloat16*)iwmp, n2);
        n2 = (size_t)DMODEL*DINNER/2;
        split_kernel<<<(unsigned)((n2 + 255)/256), 256>>>(out_w, (__nv_bfloat16*)owhp, (__nv_bfloat16*)owmp, n2);
    }

    // 3. in_proj GEMM (bf16x3): (8192 x 2048) @ (8352 x 2048)^T
    dim3 g1((DPROJ + 127)/128, TOKENS/128);
    gemm_bf16x3_kernel<<<g1, 256, gemm_smem>>>(
        (const __nv_bfloat16*)uhp, (const __nv_bfloat16*)ump,
        (const __nv_bfloat16*)iwhp, (const __nv_bfloat16*)iwmp,
        in_b, (float*)zxp, TOKENS, DPROJ, DMODEL);

    // 4. dt head in fp32 (error here is exponentially amplified -> keep exact)
    dtgemm_kernel<<<TOKENS/8, 256>>>(u, in_w, in_b, dt_bias);

    // 5. per-chunk cumsum of A*dt
    cumsum_kernel<<<BATCH*NCHUNK*NHEADS, CHUNK>>>(A_log);

    // 6. depthwise conv + silu
    conv_silu_kernel<<<((size_t)TOKENS*(CONVDIM/4))/256, 256>>>(conv_w, conv_b);

    // 7. per-chunk states
    states_kernel<<<BATCH*NCHUNK*NHEADS, 256, states_smem>>>();

    // 8. inter-chunk scan
    scan_kernel<<<BATCH*NHEADS, 256>>>();

    // 9. fused diag + off-chunk Y
    ydiag_kernel<<<BATCH*NCHUNK*NHEADS, 512, ydiag_smem>>>();

    // 10. gate + LayerNorm -> bf16 split
    gate_ln_kernel<<<TOKENS, 512>>>(ln_w, ln_b);

    // 11. out_proj GEMM (bf16x3): (8192 x 4096) @ (2048 x 4096)^T -> d_out
    dim3 g2(DMODEL/128, TOKENS/128);
    gemm_bf16x3_kernel<<<g2, 256, gemm_smem>>>(
        (const __nv_bfloat16*)yhp, (const __nv_bfloat16*)ymp,
        (const __nv_bfloat16*)owhp, (const __nv_bfloat16*)owmp,
        out_b, out, TOKENS, DMODEL, DINNER);
}

// round 6
// speedup vs baseline: 1.5270x; 1.0945x over previous
#include <cuda_runtime.h>
#include <cuda_bf16.h>
#include <math.h>
#include <stdint.h>

// ---------------- problem constants ----------------
#define BATCH    2
#define SEQ      4096
#define DMODEL   2048
#define DSTATE   64
#define HEADDIM  128
#define CHUNK    256
#define DINNER   4096
#define NHEADS   32
#define CONVDIM  4224               // DINNER + 2*DSTATE
#define DPROJ    8352               // 2*DINNER + 2*DSTATE + NHEADS
#define NCHUNK   16                 // SEQ / CHUNK
#define TOKENS   (BATCH*SEQ)        // 8192
#define LN_EPS   1e-5f

// ---------------- device scratch (no cudaMalloc allowed) ----------------
__device__ float g_zx [(size_t)TOKENS * DPROJ];    // in_proj output
__device__ float g_xbc[(size_t)TOKENS * CONVDIM];  // conv+silu output
__device__ float g_dt [TOKENS * NHEADS];           // softplus(dt)
__device__ float g_cA [BATCH*NCHUNK*NHEADS*CHUNK]; // per-chunk cumsum of A*dt
__device__ float g_st [BATCH*NCHUNK*NHEADS*HEADDIM*DSTATE]; // chunk states
__device__ float g_stP[BATCH*NCHUNK*NHEADS*HEADDIM*DSTATE]; // prefix states
__device__ float g_y  [(size_t)TOKENS * DINNER];   // SSD output (pre-LN)

// bf16 hi/mid split operands for the tensor-core GEMMs
__device__ __nv_bfloat16 g_uh [(size_t)TOKENS * DMODEL];
__device__ __nv_bfloat16 g_um [(size_t)TOKENS * DMODEL];
__device__ __nv_bfloat16 g_iwh[(size_t)DPROJ  * DMODEL];
__device__ __nv_bfloat16 g_iwm[(size_t)DPROJ  * DMODEL];
__device__ __nv_bfloat16 g_owh[(size_t)DMODEL * DINNER];
__device__ __nv_bfloat16 g_owm[(size_t)DMODEL * DINNER];
__device__ __nv_bfloat16 g_yh [(size_t)TOKENS * DINNER];
__device__ __nv_bfloat16 g_ym [(size_t)TOKENS * DINNER];

// ---------------- helpers ----------------
__device__ __forceinline__ void bsplit(float x, __nv_bfloat16& h, __nv_bfloat16& m) {
    h = __float2bfloat16(x);
    m = __float2bfloat16(x - __bfloat162float(h));
}
__device__ __forceinline__ void cp_async16(uint32_t dst, const void* src, int sz) {
    asm volatile("cp.async.ca.shared.global [%0], [%1], 16, %2;\n"
                 :: "r"(dst), "l"(src), "r"(sz));
}
#define CP_COMMIT() asm volatile("cp.async.commit_group;\n")
#define CP_WAIT1()  asm volatile("cp.async.wait_group 1;\n")
#define CP_WAIT0()  asm volatile("cp.async.wait_group 0;\n")

#define MMA_BF16(d, a0,a1,a2,a3, b0,b1)                                      \
    asm volatile("mma.sync.aligned.m16n8k16.row.col.f32.bf16.bf16.f32 "      \
        "{%0,%1,%2,%3}, {%4,%5,%6,%7}, {%8,%9}, {%0,%1,%2,%3};"              \
        : "+f"(d[0]), "+f"(d[1]), "+f"(d[2]), "+f"(d[3])                     \
        : "r"(a0), "r"(a1), "r"(a2), "r"(a3), "r"(b0), "r"(b1))

#define LDSM_X4(r0,r1,r2,r3, addr)                                           \
    asm volatile("ldmatrix.sync.aligned.m8n8.x4.shared.b16 {%0,%1,%2,%3}, [%4];" \
        : "=r"(r0), "=r"(r1), "=r"(r2), "=r"(r3) : "r"(addr))

// ---------------- split kernels: f32 -> (bf16 hi, bf16 mid) ----------------
__global__ void split_kernel(const float* __restrict__ src,
                             __nv_bfloat16* __restrict__ hi,
                             __nv_bfloat16* __restrict__ mid, size_t n2)
{
    size_t i = (size_t)blockIdx.x * blockDim.x + threadIdx.x;
    if (i >= n2) return;
    float2 v = ((const float2*)src)[i];
    __nv_bfloat16 h0, m0, h1, m1;
    bsplit(v.x, h0, m0); bsplit(v.y, h1, m1);
    ((__nv_bfloat162*)hi)[i]  = __halves2bfloat162(h0, h1);
    ((__nv_bfloat162*)mid)[i] = __halves2bfloat162(m0, m1);
}

// ================= bf16x3 tensor-core GEMM (ldmatrix fragments) =================
// C[M,N] = (Ah+Am)[M,K] @ (Wh+Wm)[N,K]^T + bias,  D += AhWh + AhWm + AmWh.
// 256 threads, block tile 128x128x32, warp tile 64x32, mma.m16n8k16.bf16.
// smem rows padded to 40 bf16 (80B, stride 20 words): ldmatrix row offsets mod 32
// words = {0,20,8,28,16,4,24,12} -> all 8 rows hit disjoint 4-word chunks.

#define SW 20                 // smem row stride in 32-bit words
#define TSZ (128*40)          // bf16 elements per tile array
#define TILEBYTES (TSZ*2)     // 10240 B

__global__ __launch_bounds__(256) void gemm_bf16x3_kernel(
    const __nv_bfloat16* __restrict__ Ah, const __nv_bfloat16* __restrict__ Am,
    const __nv_bfloat16* __restrict__ Wh, const __nv_bfloat16* __restrict__ Wm,
    const float* __restrict__ bias, float* __restrict__ C,
    int M, int N, int K)
{
    extern __shared__ __nv_bfloat16 sh[];   // [2 stages][4 arrays][128][40]
    const uint32_t sm_base = (uint32_t)__cvta_generic_to_shared(sh);

    const int t    = threadIdx.x;
    const int bm   = blockIdx.y * 128;
    const int bn   = blockIdx.x * 128;
    const int lane = t & 31;
    const int warp = t >> 5;
    const int wm   = (warp >> 2) * 64;
    const int wn   = (warp & 3) * 32;
    const int gid  = lane >> 2, tig = lane & 3;

    const int lrow = t >> 2;       // 0..63
    const int lch  = t & 3;        // 16B chunk within a 64B row

    // ldmatrix per-lane source row/col selectors
    const int aRow = (lane & 7) + ((lane >> 3) & 1) * 8;   // A: M1 = rows 8-15 (k0-7)
    const int aK   = ((lane >> 4) & 1) * 16;               //    M2/M3 = +16B (k8-15)
    const int bRow = (lane & 7) + ((lane >> 4) & 1) * 8;   // B: M2/M3 = rows 8-15
    const int bK   = ((lane >> 3) & 1) * 16;               //    M1/M3 = +16B

    float acc[4][4][4];
#pragma unroll
    for (int i = 0; i < 4; i++)
#pragma unroll
        for (int j = 0; j < 4; j++)
#pragma unroll
            for (int k = 0; k < 4; k++) acc[i][j][k] = 0.f;

    const int nk = K / 32;

#define LOAD_STAGE(stg, kb) do {                                                       \
    _Pragma("unroll")                                                                  \
    for (int p = 0; p < 2; p++) {                                                      \
        int r = p*64 + lrow;                                                           \
        uint32_t db = sm_base + (uint32_t)(((stg)*4*TSZ + r*40)*2 + lch*16);           \
        cp_async16(db,             Ah + (size_t)(bm + r)*K + (kb)*32 + lch*8, 16);     \
        cp_async16(db + TILEBYTES, Am + (size_t)(bm + r)*K + (kb)*32 + lch*8, 16);     \
        int ok = (bn + r) < N;                                                         \
        const __nv_bfloat16* wsh = Wh + (size_t)(ok ? (bn + r) : 0)*K + (kb)*32 + lch*8; \
        const __nv_bfloat16* wsm = Wm + (size_t)(ok ? (bn + r) : 0)*K + (kb)*32 + lch*8; \
        cp_async16(db + 2*TILEBYTES, wsh, ok ? 16 : 0);                                \
        cp_async16(db + 3*TILEBYTES, wsm, ok ? 16 : 0);                                \
    }                                                                                  \
    CP_COMMIT(); } while (0)

    LOAD_STAGE(0, 0);

    for (int kb = 0; kb < nk; kb++) {
        if (kb + 1 < nk) {
            LOAD_STAGE((kb + 1) & 1, kb + 1);
            CP_WAIT1();
        } else {
            CP_WAIT0();
        }
        __syncthreads();

        const uint32_t stB = sm_base + (uint32_t)((kb & 1)*4*TILEBYTES);
        const uint32_t aB  = stB + (uint32_t)((wm + aRow)*80 + aK);
        const uint32_t bB  = stB + 2*TILEBYTES + (uint32_t)((wn + bRow)*80 + bK);

#pragma unroll
        for (int kk = 0; kk < 2; kk++) {
            const uint32_t ko = kk*32;
            uint32_t bh[4][2], bm_[4][2];
#pragma unroll
            for (int p = 0; p < 2; p++) {
                uint32_t ab = bB + p*1280 + ko;   // 16 rows * 80B
                LDSM_X4(bh[2*p][0],  bh[2*p][1],  bh[2*p+1][0],  bh[2*p+1][1],  ab);
                LDSM_X4(bm_[2*p][0], bm_[2*p][1], bm_[2*p+1][0], bm_[2*p+1][1], ab + TILEBYTES);
            }
#pragma unroll
            for (int mt = 0; mt < 4; mt++) {
                uint32_t aa = aB + mt*1280 + ko;
                uint32_t a0,a1,a2,a3, m0,m1,m2,m3;
                LDSM_X4(a0,a1,a2,a3, aa);
                LDSM_X4(m0,m1,m2,m3, aa + TILEBYTES);
#pragma unroll
                for (int nt = 0; nt < 4; nt++) {
                    MMA_BF16(acc[mt][nt], a0,a1,a2,a3, bh[nt][0],  bh[nt][1]);
                    MMA_BF16(acc[mt][nt], a0,a1,a2,a3, bm_[nt][0], bm_[nt][1]);
                    MMA_BF16(acc[mt][nt], m0,m1,m2,m3, bh[nt][0],  bh[nt][1]);
                }
            }
        }
        __syncthreads();
    }

    // ---- epilogue (c-frag: rows gid/gid+8, cols tig*2, tig*2+1) ----
#pragma unroll
    for (int mt = 0; mt < 4; mt++) {
        int r0 = bm + wm + mt*16 + gid;
#pragma unroll
        for (int nt = 0; nt < 4; nt++) {
            int c0 = bn + wn + nt*8 + tig*2;
            if (c0 < N) {   // N even, c0 even -> c0+1 also valid
                float b0v = bias[c0], b1v = bias[c0+1];
                float2 v0 = make_float2(acc[mt][nt][0] + b0v, acc[mt][nt][1] + b1v);
                float2 v1 = make_float2(acc[mt][nt][2] + b0v, acc[mt][nt][3] + b1v);
                *(float2*)&C[(size_t)r0*N + c0]     = v0;
                *(float2*)&C[(size_t)(r0+8)*N + c0] = v1;
            }
        }
    }
#undef LOAD_STAGE
}

// ---------------- fp32 GEMM for the dt head (32 cols) + softplus ----------------
__global__ __launch_bounds__(256) void dtgemm_kernel(
    const float* __restrict__ u, const float* __restrict__ w,
    const float* __restrict__ in_b, const float* __restrict__ dt_bias)
{
    int warp = threadIdx.x >> 5, lane = threadIdx.x & 31;
    int tok = blockIdx.x * 8 + warp;
    const float4* u4 = (const float4*)(u + (size_t)tok * DMODEL);
    const float4* w4 = (const float4*)(w + (size_t)(DINNER + CONVDIM + lane) * DMODEL);
    float acc = 0.f;
#pragma unroll 4
    for (int k = 0; k < DMODEL/4; k++) {
        float4 a = u4[k], b = w4[k];
        acc += a.x*b.x + a.y*b.y + a.z*b.z + a.w*b.w;
    }
    float x = acc + in_b[DINNER + CONVDIM + lane] + dt_bias[lane];
    g_dt[tok*NHEADS + lane] = (x > 20.f) ? x : log1pf(expf(x));
}

// ---------------- causal depthwise conv (k=4) + silu, float4 over channels ----------------
__global__ void conv_silu_kernel(const float* __restrict__ cw, const float* __restrict__ cb)
{
    int idx = blockIdx.x * blockDim.x + threadIdx.x;   // TOKENS*CONVDIM/4
    int ch4 = idx % (CONVDIM/4);
    int tok = idx / (CONVDIM/4);
    int ch  = ch4 * 4;
    int l   = tok & (SEQ - 1);

    float4 a = *(const float4*)(cb + ch);
    float acc[4] = {a.x, a.y, a.z, a.w};
    float w[4][4];
#pragma unroll
    for (int c = 0; c < 4; c++)
        *(float4*)w[c] = *(const float4*)(cw + (ch + c)*4);

    const float* base = g_zx + (size_t)tok * DPROJ + DINNER + ch;
#pragma unroll
    for (int k = 0; k < 4; k++) {
        int ls = l - 3 + k;
        if (ls >= 0) {
            float4 x = *(const float4*)(base + (long)(k-3) * DPROJ);
            acc[0] += w[0][k]*x.x; acc[1] += w[1][k]*x.y;
            acc[2] += w[2][k]*x.z; acc[3] += w[3][k]*x.w;
        }
    }
    float4 o;
    o.x = acc[0] / (1.f + __expf(-acc[0]));
    o.y = acc[1] / (1.f + __expf(-acc[1]));
    o.z = acc[2] / (1.f + __expf(-acc[2]));
    o.w = acc[3] / (1.f + __expf(-acc[3]));
    *(float4*)(g_xbc + (size_t)tok * CONVDIM + ch) = o;
}

// ---------------- per-chunk inclusive cumsum of dA = A*dt ----------------
__global__ void cumsum_kernel(const float* __restrict__ A_log)
{
    __shared__ float s[CHUNK];
    int bid = blockIdx.x;                     // ((b*NCHUNK+c)*NHEADS+h)
    int h = bid & 31;
    int c = (bid >> 5) & 15;
    int b = bid >> 9;
    int l = threadIdx.x;
    int tok = b*SEQ + c*CHUNK + l;
    float Av = -expf(A_log[h]);
    s[l] = Av * g_dt[tok*NHEADS + h];
    __syncthreads();
    for (int off = 1; off < CHUNK; off <<= 1) {
        float add = (l >= off) ? s[l-off] : 0.f;
        __syncthreads();
        s[l] += add;
        __syncthreads();
    }
    g_cA[bid*CHUNK + l] = s[l];
}

// ---------------- per-chunk states: S[p,n] = sum_s decay[s]*dt[s]*x[s,p]*B[s,n] ----------------
__global__ __launch_bounds__(256) void states_kernel()
{
    extern __shared__ float sm[];
    float* sBw  = sm;            // 64*64
    float* sX   = sm + 4096;     // 64*128
    float* sdec = sX + 8192;     // 64
    float* sdtv = sdec + 64;     // 64
    int bid = blockIdx.x;
    int h = bid & 31, c = (bid >> 5) & 15, b = bid >> 9;
    int tok0 = b*SEQ + c*CHUNK;
    const float* cA = g_cA + bid*CHUNK;
    int t = threadIdx.x;
    float cAlast = cA[CHUNK-1];
    int tp = t & 31, tn = t >> 5;
    float acc[4][8];
#pragma unroll
    for (int i = 0; i < 4; i++)
#pragma unroll
        for (int j = 0; j < 8; j++) acc[i][j] = 0.f;

    for (int s0 = 0; s0 < CHUNK; s0 += 64) {
        __syncthreads();
        if (t < 64) {
            sdec[t] = __expf(cAlast - cA[s0 + t]);
            sdtv[t] = g_dt[(tok0 + s0 + t)*NHEADS + h];
        }
        __syncthreads();
#pragma unroll
        for (int i = 0; i < 16; i++) {
            int idx = i*256 + t; int s = idx >> 6, n = idx & 63;
            sBw[idx] = g_xbc[(size_t)(tok0+s0+s)*CONVDIM + DINNER + n] * sdec[s];
        }
#pragma unroll
        for (int i = 0; i < 32; i++) {
            int idx = i*256 + t; int s = idx >> 7, p = idx & 127;
            sX[idx] = g_xbc[(size_t)(tok0+s0+s)*CONVDIM + h*HEADDIM + p] * sdtv[s];
        }
        __syncthreads();
        for (int s = 0; s < 64; s++) {
            float4 xa = *(const float4*)&sX[s*128 + tp*4];
            float bb[8];
            *(float4*)&bb[0] = *(const float4*)&sBw[s*64 + tn*8];
            *(float4*)&bb[4] = *(const float4*)&sBw[s*64 + tn*8 + 4];
            float xf[4] = {xa.x, xa.y, xa.z, xa.w};
#pragma unroll
            for (int i = 0; i < 4; i++)
#pragma unroll
                for (int j = 0; j < 8; j++) acc[i][j] += xf[i]*bb[j];
        }
    }
    float* out = g_st + (size_t)bid * HEADDIM * DSTATE;
#pragma unroll
    for (int i = 0; i < 4; i++)
#pragma unroll
        for (int j = 0; j < 8; j++)
            out[(tp*4 + i)*DSTATE + tn*8 + j] = acc[i][j];
}

// ---------------- inter-chunk sequential scan (16 steps per (b,h)) ----------------
__global__ void scan_kernel()
{
    int bh = blockIdx.x;           // b*NHEADS + h
    int h = bh & 31, b = bh >> 5;
    int t = threadIdx.x;           // 256
    float P[32];
#pragma unroll
    for (int i = 0; i < 32; i++) P[i] = 0.f;
    for (int c = 0; c < NCHUNK; c++) {
        int cb = (b*NCHUNK + c)*NHEADS + h;
        float dec = __expf(g_cA[cb*CHUNK + CHUNK-1]);
        size_t sb = (size_t)cb * HEADDIM * DSTATE;
#pragma unroll
        for (int i = 0; i < 32; i++) {
            int e = i*256 + t;
            g_stP[sb + e] = P[i];
            P[i] = P[i]*dec + g_st[sb + e];
        }
    }
}

// ---------------- fused Y = (L ∘ C B^T) X·dt + exp(cumA) C S_prev^T ----------------
#define Y_PHASE2_STEP()                                                  \
    for (int s = 0; s < 64; s++) {                                       \
        float afr[8];                                                    \
        _Pragma("unroll")                                                \
        for (int i = 0; i < 8; i++) afr[i] = sG[(tl*8 + i)*65 + s];      \
        float bfr[8];                                                    \
        *(float4*)&bfr[0] = *(const float4*)&sX[s*128 + tp*8];           \
        *(float4*)&bfr[4] = *(const float4*)&sX[s*128 + tp*8 + 4];       \
        _Pragma("unroll")                                                \
        for (int i = 0; i < 8; i++)                                      \
            _Pragma("unroll")                                            \
            for (int j = 0; j < 8; j++) acc[i][j] += afr[i]*bfr[j];      \
    }

__global__ __launch_bounds__(512) void ydiag_kernel()
{
    extern __shared__ float sm[];
    float* scA   = sm;                 // 256
    float* srowf = scA + 256;          // 256
    float* scolf = srowf + 256;        // 64
    float* sdtv  = scolf + 64;         // 64
    float* sC    = sdtv + 64;          // 256*64
    float* sB    = sC + 16384;         // 64*65 (padded)
    float* sX    = sB + 4160;          // 64*128
    float* sG    = sX + 8192;          // 256*65 (padded)

    int bid = blockIdx.x;
    int h = bid & 31, c = (bid >> 5) & 15, b = bid >> 9;
    int tok0 = b*SEQ + c*CHUNK;
    int t = threadIdx.x;
    const float* cAg = g_cA + bid*CHUNK;

    const int tl = t >> 4;   // 0..31 : l-tile (8 rows each)
    const int tp = t & 15;   // 0..15 : p-tile (8 cols each)

    float acc[8][8];
#pragma unroll
    for (int i = 0; i < 8; i++)
#pragma unroll
        for (int j = 0; j < 8; j++) acc[i][j] = 0.f;

    if (t < 256) scA[t] = cAg[t];
#pragma unroll
    for (int i = 0; i < 32; i++) {
        int idx = i*512 + t; int l = idx >> 6, n = idx & 63;
        sC[idx] = g_xbc[(size_t)(tok0 + l)*CONVDIM + DINNER + DSTATE + n];
    }
    {   // S_prev transposed into sX:  sX[n*128+p] = S_prev[p,n]
        size_t sb = (size_t)bid * HEADDIM * DSTATE;
#pragma unroll
        for (int i = 0; i < 16; i++) {
            int idx = i*512 + t; int n = idx >> 7, p = idx & 127;
            sX[idx] = g_stP[sb + p*DSTATE + n];
        }
    }
    __syncthreads();
    if (t < 256) srowf[t] = __expf(scA[t]);
    __syncthreads();
#pragma unroll
    for (int i = 0; i < 32; i++) {   // G0[l,n] = C[l,n]*exp(cumA[l])
        int idx = i*512 + t; int l = idx >> 6, n = idx & 63;
        sG[l*65 + n] = sC[idx] * srowf[l];
    }
    __syncthreads();
    Y_PHASE2_STEP();                 // off-chunk contribution

    for (int s0 = 0; s0 < CHUNK; s0 += 64) {
        __syncthreads();             // previous phase-2 done
        float cAe = scA[s0 + 63];
        if (t < 64) {
            sdtv[t]  = g_dt[(tok0 + s0 + t)*NHEADS + h];
            scolf[t] = __expf(cAe - scA[s0 + t]);          // <= 1
        }
        if (t < 256) srowf[t] = __expf(scA[t] - cAe);      // used only for l >= s0+64
#pragma unroll
        for (int i = 0; i < 8; i++) {
            int idx = i*512 + t; int s = idx >> 6, n = idx & 63;
            sB[s*65 + n] = g_xbc[(size_t)(tok0+s0+s)*CONVDIM + DINNER + n];
        }
        __syncthreads();
#pragma unroll
        for (int i = 0; i < 16; i++) {
            int idx = i*512 + t; int s = idx >> 7, p = idx & 127;
            sX[idx] = g_xbc[(size_t)(tok0+s0+s)*CONVDIM + h*HEADDIM + p] * sdtv[s];
        }
        // phase 1: G[l,s] = (C[l]·B[s]) * exp(cumA[l]-cumA[s]) masked
#pragma unroll
        for (int g = 0; g < 2; g++) {
            float a1[4][4];
#pragma unroll
            for (int i = 0; i < 4; i++)
#pragma unroll
                for (int j = 0; j < 4; j++) a1[i][j] = 0.f;
            for (int n = 0; n < 64; n++) {
                float cc[4], bb[4];
#pragma unroll
                for (int i = 0; i < 4; i++) cc[i] = sC[(tl*8 + g*4 + i)*64 + n];
#pragma unroll
                for (int j = 0; j < 4; j++) bb[j] = sB[(tp*4 + j)*65 + n];
#pragma unroll
                for (int i = 0; i < 4; i++)
#pragma unroll
                    for (int j = 0; j < 4; j++) a1[i][j] += cc[i]*bb[j];
            }
#pragma unroll
            for (int i = 0; i < 4; i++) {
                int l = tl*8 + g*4 + i;
#pragma unroll
                for (int j = 0; j < 4; j++) {
                    int s  = tp*4 + j;
                    int sg = s0 + s;
                    float w;
                    if (l < sg)            w = 0.f;
                    else if (l < s0 + 64)  w = __expf(scA[l] - scA[sg]);   // diagonal tile
                    else                   w = srowf[l] * scolf[s];        // factored, both <= 1
                    sG[l*65 + s] = a1[i][j] * w;
                }
            }
        }
        __syncthreads();
        Y_PHASE2_STEP();
    }

    float* yout = g_y + (size_t)tok0 * DINNER + h*HEADDIM;
#pragma unroll
    for (int i = 0; i < 8; i++) {
        int l = tl*8 + i;
#pragma unroll
        for (int j = 0; j < 8; j += 4) {
            float4 v = make_float4(acc[i][j], acc[i][j+1], acc[i][j+2], acc[i][j+3]);
            *(float4*)&yout[(size_t)l*DINNER + tp*8 + j] = v;
        }
    }
}

// ---------------- gate (y * silu(z)) + LayerNorm -> bf16 hi/mid split ----------------
__global__ __launch_bounds__(512) void gate_ln_kernel(
    const float* __restrict__ lnw, const float* __restrict__ lnb)
{
    int tok = blockIdx.x;
    int t = threadIdx.x;
    const float* zx = g_zx + (size_t)tok * DPROJ;
    const float* y = g_y + (size_t)tok * DINNER;
    __shared__ float rbuf[16];
    __shared__ float stat[2];

    float v[8];
    float sum = 0.f;
#pragma unroll
    for (int i = 0; i < 8; i++) {
        int e = i*512 + t;
        float z = zx[e];
        float g = y[e] * z / (1.f + __expf(-z));
        v[i] = g; sum += g;
    }
#pragma unroll
    for (int o = 16; o; o >>= 1) sum += __shfl_xor_sync(0xffffffffu, sum, o);
    if ((t & 31) == 0) rbuf[t >> 5] = sum;
    __syncthreads();
    if (t == 0) {
        float x = 0.f;
        for (int i = 0; i < 16; i++) x += rbuf[i];
        stat[0] = x * (1.f / DINNER);
    }
    __syncthreads();
    float mu = stat[0];
    float s2 = 0.f;
#pragma unroll
    for (int i = 0; i < 8; i++) { float d = v[i] - mu; s2 += d*d; }
#pragma unroll
    for (int o = 16; o; o >>= 1) s2 += __shfl_xor_sync(0xffffffffu, s2, o);
    if ((t & 31) == 0) rbuf[t >> 5] = s2;
    __syncthreads();
    if (t == 0) {
        float x = 0.f;
        for (int i = 0; i < 16; i++) x += rbuf[i];
        stat[1] = rsqrtf(x * (1.f / DINNER) + LN_EPS);
    }
    __syncthreads();
    float inv = stat[1];
    size_t base = (size_t)tok * DINNER;
#pragma unroll
    for (int i = 0; i < 8; i++) {
        int e = i*512 + t;
        float r = (v[i] - mu) * inv * lnw[e] + lnb[e];
        __nv_bfloat16 h, m;
        bsplit(r, h, m);
        g_yh[base + e] = h;
        g_ym[base + e] = m;
    }
}

// ---------------- launch ----------------
extern "C" void kernel_launch(void* const* d_in, const int* in_sizes, int n_in,
                              void* d_out, int out_size)
{
    const float* u       = (const float*)d_in[0];
    const float* in_w    = (const float*)d_in[1];
    const float* in_b    = (const float*)d_in[2];
    const float* conv_w  = (const float*)d_in[3];
    const float* conv_b  = (const float*)d_in[4];
    const float* dt_bias = (const float*)d_in[5];
    const float* A_log   = (const float*)d_in[6];
    const float* ln_w    = (const float*)d_in[7];
    const float* ln_b    = (const float*)d_in[8];
    const float* out_w   = (const float*)d_in[9];
    const float* out_b   = (const float*)d_in[10];
    float* out = (float*)d_out;

    void *zxp, *uhp, *ump, *iwhp, *iwmp, *owhp, *owmp, *yhp, *ymp;
    cudaGetSymbolAddress(&zxp,  g_zx);
    cudaGetSymbolAddress(&uhp,  g_uh);  cudaGetSymbolAddress(&ump,  g_um);
    cudaGetSymbolAddress(&iwhp, g_iwh); cudaGetSymbolAddress(&iwmp, g_iwm);
    cudaGetSymbolAddress(&owhp, g_owh); cudaGetSymbolAddress(&owmp, g_owm);
    cudaGetSymbolAddress(&yhp,  g_yh);  cudaGetSymbolAddress(&ymp,  g_ym);

    const int gemm_smem   = 2 * 4 * TSZ * 2;                           // 81,920 B
    const int states_smem = (4096 + 8192 + 64 + 64) * 4;               // 49,664 B
    const int ydiag_smem  = (256+256+64+64 + 16384 + 4160 + 8192 + 16640) * 4; // 184,064 B
    cudaFuncSetAttribute(gemm_bf16x3_kernel, cudaFuncAttributeMaxDynamicSharedMemorySize, gemm_smem);
    cudaFuncSetAttribute(states_kernel, cudaFuncAttributeMaxDynamicSharedMemorySize, states_smem);
    cudaFuncSetAttribute(ydiag_kernel,  cudaFuncAttributeMaxDynamicSharedMemorySize, ydiag_smem);

    // 0-2. bf16 hi/mid splits of u, in_w, out_w
    {
        size_t n2;
        n2 = (size_t)TOKENS*DMODEL/2;
        split_kernel<<<(unsigned)((n2 + 255)/256), 256>>>(u, (__nv_bfloat16*)uhp, (__nv_bfloat16*)ump, n2);
        n2 = (size_t)DPROJ*DMODEL/2;
        split_kernel<<<(unsigned)((n2 + 255)/256), 256>>>(in_w, (__nv_bfloat16*)iwhp, (__nv_bfloat16*)iwmp, n2);
        n2 = (size_t)DMODEL*DINNER/2;
        split_kernel<<<(unsigned)((n2 + 255)/256), 256>>>(out_w, (__nv_bfloat16*)owhp, (__nv_bfloat16*)owmp, n2);
    }

    // 3. in_proj GEMM (bf16x3): (8192 x 2048) @ (8352 x 2048)^T
    dim3 g1((DPROJ + 127)/128, TOKENS/128);
    gemm_bf16x3_kernel<<<g1, 256, gemm_smem>>>(
        (const __nv_bfloat16*)uhp, (const __nv_bfloat16*)ump,
        (const __nv_bfloat16*)iwhp, (const __nv_bfloat16*)iwmp,
        in_b, (float*)zxp, TOKENS, DPROJ, DMODEL);

    // 4. dt head in fp32 (error here is exponentially amplified -> keep exact)
    dtgemm_kernel<<<TOKENS/8, 256>>>(u, in_w, in_b, dt_bias);

    // 5. per-chunk cumsum of A*dt
    cumsum_kernel<<<BATCH*NCHUNK*NHEADS, CHUNK>>>(A_log);

    // 6. depthwise conv + silu
    conv_silu_kernel<<<((size_t)TOKENS*(CONVDIM/4))/256, 256>>>(conv_w, conv_b);

    // 7. per-chunk states
    states_kernel<<<BATCH*NCHUNK*NHEADS, 256, states_smem>>>();

    // 8. inter-chunk scan
    scan_kernel<<<BATCH*NHEADS, 256>>>();

    // 9. fused diag + off-chunk Y
    ydiag_kernel<<<BATCH*NCHUNK*NHEADS, 512, ydiag_smem>>>();

    // 10. gate + LayerNorm -> bf16 split
    gate_ln_kernel<<<TOKENS, 512>>>(ln_w, ln_b);

    // 11. out_proj GEMM (bf16x3): (8192 x 4096) @ (2048 x 4096)^T -> d_out
    dim3 g2(DMODEL/128, TOKENS/128);
    gemm_bf16x3_kernel<<<g2, 256, gemm_smem>>>(
        (const __nv_bfloat16*)yhp, (const __nv_bfloat16*)ymp,
        (const __nv_bfloat16*)owhp, (const __nv_bfloat16*)owmp,
        out_b, out, TOKENS, DMODEL, DINNER);
}